// round 9
// baseline (speedup 1.0000x reference)
#include <cuda_runtime.h>
#include <math_constants.h>

// RoIPool, warp-cooperative, single-pass row scan, float2 lanes, unroll-4
// pipeline, PREDICATED loads (only needed columns / valid rows touch L1).
// feature [B,C,152,152] f32, rois [N,5] f32, out [N,C,7,7] f32.
// One warp = (roi n, 4 consecutive channels).
//   Columns: xs0 = xs & ~1, d = xs - xs0. Half-warp hw covers channels c0+hw
//   (reg A) and c0+2+hw (reg B); lane ln loads float2 at position 2*ln.
//   Only lanes with 2*ln <= d+roiw are active (phase 2 reads positions
//   d..d+roiw); inactive lanes carry -inf and skip LDG/STS entirely.
//   Rows: scan ys..hlast = ys+ceil(7*binh)-1 once; bins tile with <=1-row
//   overlap; several bins may close on one row (do/while). 4-stage register
//   ring with prefetch distance 4; out-of-range refills are predicated off
//   (stage = -inf; consumed only by never-stored tail iterations).
// Bin sizes = roiX * fl(1/7) (reciprocal multiply) to match XLA bit-exactly.

#define PH 7
#define PW 7
#define HF 152
#define WF 152
#define CPW 4
#define WARPS 8

__global__ __launch_bounds__(256) void roipool_f2p_kernel(
    const float* __restrict__ feat,
    const float* __restrict__ rois,
    const int* __restrict__ stride_p,
    float* __restrict__ out,
    int C, int gpr)
{
    __shared__ __align__(16) float rm[WARPS][CPW][PH][34];

    int si = *stride_p;
    float stride_f = (si > 0 && si <= 65536) ? (float)si : __int_as_float(si);
    const float scale = 1.0f / stride_f;

    const int warpId = threadIdx.x >> 5;
    const int lane   = threadIdx.x & 31;
    const int hw = lane >> 4;          // half-warp -> sub-channel
    const int ln = lane & 15;          // lane within half-warp -> column pair
    const int wg = blockIdx.x * WARPS + warpId;
    const int n  = wg / gpr;
    const int cg = wg - n * gpr;
    const int c0 = cg * CPW;

    const float* r = rois + n * 5;
    const int b  = (int)r[0];
    const int xs = (int)rintf(r[1] * scale);   // round-half-even, matches jnp.round
    const int ys = (int)rintf(r[2] * scale);
    const int xe = (int)rintf(r[3] * scale);
    const int ye = (int)rintf(r[4] * scale);
    const int roih = max(ye - ys + 1, 1);
    const int roiw = max(xe - xs + 1, 1);
    const float binh = (float)roih * (1.0f / 7.0f);   // reciprocal multiply (bit-exact)
    const float binw = (float)roiw * (1.0f / 7.0f);

    const int xs0 = xs & ~1;
    const int d   = xs - xs0;
    // phase 2 reads positions d .. d+roiw; pair needed iff 2*ln <= d+roiw
    const bool act = (2 * ln) <= (d + roiw);
    const int  c2  = min(xs0 + 2 * ln, WF - 2);       // safe addr even if inactive

    const size_t cs = (size_t)HF * WF;
    const float* fA = feat + ((size_t)(b * C + c0 + hw)) * cs + c2;  // ch c0+hw
    const float* fB = fA + 2 * cs;                                    // ch c0+2+hw

    const int hlast = ys + (int)ceilf(7.0f * binh) - 1;   // <= ye+1 <= 151
    int ph   = 0;
    int hcut = ys + (int)ceilf(binh);                     // hend of bin 0

    const float2 NEG2 = make_float2(-CUDART_INF_F, -CUDART_INF_F);

    // 4-stage preload, predicated (row-valid AND column-active)
    float2 sA[4], sB[4];
    #pragma unroll
    for (int j = 0; j < 4; ++j) {
        const int hj = ys + j;
        const bool v = act && (hj <= hlast);
        float2 tA = NEG2, tB = NEG2;
        if (v) { tA = *(const float2*)(fA + hj * WF);
                 tB = *(const float2*)(fB + hj * WF); }
        sA[j] = tA; sB[j] = tB;
    }
    float2 mA = NEG2, mB = NEG2;

    const int T = hlast - ys + 1;
    for (int k = 0; k < T; k += 4) {
        #pragma unroll
        for (int j = 0; j < 4; ++j) {
            const int h = ys + k + j;
            const float2 aA = sA[j];
            const float2 aB = sB[j];
            // refill stage with row h+4, predicated (no clamped duplicates)
            {
                const int hn = h + 4;
                const bool v = act && (hn <= hlast);
                float2 tA = NEG2, tB = NEG2;
                if (v) { tA = *(const float2*)(fA + hn * WF);
                         tB = *(const float2*)(fB + hn * WF); }
                sA[j] = tA; sB[j] = tB;
            }

            mA.x = fmaxf(mA.x, aA.x);  mA.y = fmaxf(mA.y, aA.y);
            mB.x = fmaxf(mB.x, aB.x);  mB.y = fmaxf(mB.y, aB.y);

            if (ph < PH && h == hcut - 1) {    // warp-uniform; may close SEVERAL bins
                do {
                    if (act) {
                        const int p = 2 * ln;
                        *(float2*)&rm[warpId][hw][ph][p]     = mA;
                        *(float2*)&rm[warpId][2 + hw][ph][p] = mB;
                    }
                    // next bin starts at h (overlap) or h+1 (disjoint)
                    const int hs_next = ys + (int)floorf((float)(ph + 1) * binh);
                    const bool ov = (hs_next <= h);
                    mA.x = ov ? aA.x : -CUDART_INF_F;
                    mA.y = ov ? aA.y : -CUDART_INF_F;
                    mB.x = ov ? aB.x : -CUDART_INF_F;
                    mB.y = ov ? aB.y : -CUDART_INF_F;
                    ph++;
                    hcut = ys + (int)ceilf((float)(ph + 1) * binh);
                } while (ph < PH && h == hcut - 1);
            }
        }
    }
    __syncwarp();

    // ---- phase 2: column max per (ph,pw) bin (positions offset by d) ----
    const size_t obase = ((size_t)n * C + c0) * (PH * PW);
    #pragma unroll
    for (int rep = 0; rep < 2; ++rep) {
        int pp = rep * 32 + lane;
        if (pp < PH * PW) {
            int phh = pp / PW;
            int pw  = pp - phh * PW;
            int wsl = (int)floorf((float)pw * binw);          // local cols, >= 0
            int wel = (int)ceilf((float)(pw + 1) * binw);     // may reach roiw+1
            const int wl = wel - 1;                           // <= roiw (covered)
            #pragma unroll
            for (int ch = 0; ch < CPW; ++ch) {
                float m = -CUDART_INF_F;
                #pragma unroll
                for (int j = 0; j < 6; ++j) {                 // col-bin extent <= 6
                    m = fmaxf(m, rm[warpId][ch][phh][d + min(wsl + j, wl)]);
                }
                out[obase + (size_t)ch * (PH * PW) + pp] = m;
            }
        }
    }
}

extern "C" void kernel_launch(void* const* d_in, const int* in_sizes, int n_in,
                              void* d_out, int out_size) {
    const float* feat   = (const float*)d_in[0];
    const float* rois   = (const float*)d_in[1];
    const int*   stride = (const int*)d_in[2];
    float*       out    = (float*)d_out;

    const int N = in_sizes[1] / 5;
    const int C = out_size / (N * PH * PW);        // 256
    const int gpr = C / CPW;                       // 64
    const int total_warps = N * gpr;               // 32768
    const int blocks = (total_warps + WARPS - 1) / WARPS;   // 4096

    roipool_f2p_kernel<<<blocks, 32 * WARPS>>>(feat, rois, stride, out, C, gpr);
}

// round 10
// speedup vs baseline: 1.1796x; 1.1796x over previous
#include <cuda_runtime.h>
#include <math_constants.h>

// RoIPool, warp-cooperative, single-pass row scan, float2 lanes, unroll-4
// pipeline. Tail lanes clamp to the WINDOW'S last pair (not the feature edge),
// so every load stays inside the window's own cache lines.
// feature [B,C,152,152] f32, rois [N,5] f32, out [N,C,7,7] f32.
// One warp = (roi n, 4 consecutive channels).
//   Columns: xs0 = xs & ~1, d = xs - xs0. Half-warp hw covers channels c0+hw
//   (reg A) and c0+2+hw (reg B); lane ln loads float2 at pair index
//   min(ln, (d+roiw)>>1) — all positions phase 2 reads (d..d+roiw) are loaded
//   unclamped; tail lanes duplicate the last pair (harmless for max, same lines).
//   Rows: scan ys..hlast = ys+ceil(7*binh)-1 once; bins tile with <=1-row
//   overlap; several bins may close on one row (do/while). 4-stage register
//   ring, prefetch distance 4 (clamped rows past hlast: duplicates, never stored).
// Bin sizes = roiX * fl(1/7) (reciprocal multiply) to match XLA bit-exactly.

#define PH 7
#define PW 7
#define HF 152
#define WF 152
#define CPW 4
#define WARPS 8

__global__ __launch_bounds__(256) void roipool_f2w_kernel(
    const float* __restrict__ feat,
    const float* __restrict__ rois,
    const int* __restrict__ stride_p,
    float* __restrict__ out,
    int C, int gpr)
{
    __shared__ __align__(16) float rm[WARPS][CPW][PH][34];

    int si = *stride_p;
    float stride_f = (si > 0 && si <= 65536) ? (float)si : __int_as_float(si);
    const float scale = 1.0f / stride_f;

    const int warpId = threadIdx.x >> 5;
    const int lane   = threadIdx.x & 31;
    const int hw = lane >> 4;          // half-warp -> sub-channel
    const int ln = lane & 15;          // lane within half-warp -> column pair
    const int wg = blockIdx.x * WARPS + warpId;
    const int n  = wg / gpr;
    const int cg = wg - n * gpr;
    const int c0 = cg * CPW;

    const float* r = rois + n * 5;
    const int b  = (int)r[0];
    const int xs = (int)rintf(r[1] * scale);   // round-half-even, matches jnp.round
    const int ys = (int)rintf(r[2] * scale);
    const int xe = (int)rintf(r[3] * scale);
    const int ye = (int)rintf(r[4] * scale);
    const int roih = max(ye - ys + 1, 1);
    const int roiw = max(xe - xs + 1, 1);
    const float binh = (float)roih * (1.0f / 7.0f);   // reciprocal multiply (bit-exact)
    const float binw = (float)roiw * (1.0f / 7.0f);

    const int xs0 = xs & ~1;
    const int d   = xs - xs0;
    // last pair phase 2 can touch: position d+roiw -> pair (d+roiw)>>1.
    // Tail lanes duplicate it: loads never leave the window's cache lines.
    // xs0 + 2*((d+roiw)>>1) <= xs + roiw = xe+1 <= 151, and +1 col is the pair's
    // odd element <= 151 -> float2 never exceeds the row. (If xe+1 = 151, pair
    // base is 150: in-bounds.)
    const int plim = (d + roiw) >> 1;
    const int c2   = xs0 + 2 * min(ln, plim);

    const size_t cs = (size_t)HF * WF;
    const float* fA = feat + ((size_t)(b * C + c0 + hw)) * cs + c2;  // ch c0+hw
    const float* fB = fA + 2 * cs;                                    // ch c0+2+hw

    const int hlast = ys + (int)ceilf(7.0f * binh) - 1;   // <= ye+1 <= 151
    int ph   = 0;
    int hcut = ys + (int)ceilf(binh);                     // hend of bin 0

    // 4-stage preload (row-clamped duplicates; harmless)
    float2 sA[4], sB[4];
    #pragma unroll
    for (int j = 0; j < 4; ++j) {
        const int hj = min(ys + j, hlast);
        sA[j] = *(const float2*)(fA + hj * WF);
        sB[j] = *(const float2*)(fB + hj * WF);
    }
    float2 mA = make_float2(-CUDART_INF_F, -CUDART_INF_F);
    float2 mB = make_float2(-CUDART_INF_F, -CUDART_INF_F);

    const int T = hlast - ys + 1;
    for (int k = 0; k < T; k += 4) {
        #pragma unroll
        for (int j = 0; j < 4; ++j) {
            const int h = ys + k + j;
            const float2 aA = sA[j];
            const float2 aB = sB[j];
            // refill stage with row h+4 (clamped) — issued before the close branch
            const int hn = min(h + 4, hlast);
            sA[j] = *(const float2*)(fA + hn * WF);
            sB[j] = *(const float2*)(fB + hn * WF);

            mA.x = fmaxf(mA.x, aA.x);  mA.y = fmaxf(mA.y, aA.y);
            mB.x = fmaxf(mB.x, aB.x);  mB.y = fmaxf(mB.y, aB.y);

            if (ph < PH && h == hcut - 1) {    // warp-uniform; may close SEVERAL bins
                do {
                    const int p = 2 * ln;
                    *(float2*)&rm[warpId][hw][ph][p]     = mA;
                    *(float2*)&rm[warpId][2 + hw][ph][p] = mB;
                    // next bin starts at h (overlap) or h+1 (disjoint)
                    const int hs_next = ys + (int)floorf((float)(ph + 1) * binh);
                    const bool ov = (hs_next <= h);
                    mA.x = ov ? aA.x : -CUDART_INF_F;
                    mA.y = ov ? aA.y : -CUDART_INF_F;
                    mB.x = ov ? aB.x : -CUDART_INF_F;
                    mB.y = ov ? aB.y : -CUDART_INF_F;
                    ph++;
                    hcut = ys + (int)ceilf((float)(ph + 1) * binh);
                } while (ph < PH && h == hcut - 1);
            }
        }
    }
    __syncwarp();

    // ---- phase 2: column max per (ph,pw) bin (positions offset by d) ----
    // NOTE: tail lanes wrote duplicates of pair plim at positions 2*ln > d+roiw;
    // phase 2 never reads past d+roiw, so they are invisible.
    const size_t obase = ((size_t)n * C + c0) * (PH * PW);
    #pragma unroll
    for (int rep = 0; rep < 2; ++rep) {
        int pp = rep * 32 + lane;
        if (pp < PH * PW) {
            int phh = pp / PW;
            int pw  = pp - phh * PW;
            int wsl = (int)floorf((float)pw * binw);          // local cols, >= 0
            int wel = (int)ceilf((float)(pw + 1) * binw);     // may reach roiw+1
            const int wl = wel - 1;                           // <= roiw (covered)
            #pragma unroll
            for (int ch = 0; ch < CPW; ++ch) {
                float m = -CUDART_INF_F;
                #pragma unroll
                for (int j = 0; j < 6; ++j) {                 // col-bin extent <= 6
                    m = fmaxf(m, rm[warpId][ch][phh][d + min(wsl + j, wl)]);
                }
                out[obase + (size_t)ch * (PH * PW) + pp] = m;
            }
        }
    }
}

extern "C" void kernel_launch(void* const* d_in, const int* in_sizes, int n_in,
                              void* d_out, int out_size) {
    const float* feat   = (const float*)d_in[0];
    const float* rois   = (const float*)d_in[1];
    const int*   stride = (const int*)d_in[2];
    float*       out    = (float*)d_out;

    const int N = in_sizes[1] / 5;
    const int C = out_size / (N * PH * PW);        // 256
    const int gpr = C / CPW;                       // 64
    const int total_warps = N * gpr;               // 32768
    const int blocks = (total_warps + WARPS - 1) / WARPS;   // 4096

    roipool_f2w_kernel<<<blocks, 32 * WARPS>>>(feat, rois, stride, out, C, gpr);
}